// round 4
// baseline (speedup 1.0000x reference)
#include <cuda_runtime.h>
#include <math.h>

#define KD 64
#define MDIM 256
#define VDIM 5000
#define LMBDA 0.001f
#define NITER 6
#define VCHUNK 200
#define KSPLIT 25
#define SROW 132   // padded shared row stride (multiple of 4)

// ---------------- device scratch (no allocation allowed) ----------------
__device__ float g_AP[2][KD * MDIM];     // [0]=A=tx@fx, [1]=Py=ty@fy
__device__ float g_S[KD * KD];           // inv(sx)
__device__ float g_H[KD * KD];           // sy^T sy
__device__ float g_G[KD * KD];           // A A^T
__device__ float g_T1[KD * KD];          // Py A^T
__device__ float g_Mcat[KD * 192];       // [M2 | M1 | M0]
__device__ float g_Ncat[KD * 192];       // [M2 Ginv | M1 Ginv | M0 Ginv]
__device__ float g_Hinv[KD * KD];
__device__ float g_Ginv[KD * KD];
__device__ float g_HL[KD * KD];          // H ly + ly H
__device__ float g_LHL[KD * KD];         // ly H ly
__device__ float g_LP[KD * 128];         // [-Hinv HL | Hinv LHL]
__device__ float g_X0[KD * KD];
__device__ float g_X[KD * KD];
__device__ float g_V[KD * 192];          // X @ Ncat

// ---------------- helpers ----------------

// C[a0..a0+15][0..63] = scale * sum_k P[a][k]*Q[b][k]; row strides ldp/ldq/ldc
// (multiples of 4). Requires blockDim.x == 256.
__device__ __forceinline__ void mm_nt_16(
    const float* __restrict__ P, int ldp,
    const float* __restrict__ Q, int ldq,
    int Klen, float* __restrict__ C, int ldc, int a0, float scale) {
  const int tid = threadIdx.x;
  const int a = a0 + (tid >> 4);
  const int b0 = (tid & 15) << 2;
  float acc0 = 0.f, acc1 = 0.f, acc2 = 0.f, acc3 = 0.f;
  const float4* Pr = (const float4*)(P + a * ldp);
  const float4* Q0 = (const float4*)(Q + (b0 + 0) * ldq);
  const float4* Q1 = (const float4*)(Q + (b0 + 1) * ldq);
  const float4* Q2 = (const float4*)(Q + (b0 + 2) * ldq);
  const float4* Q3 = (const float4*)(Q + (b0 + 3) * ldq);
  const int k4 = Klen >> 2;
  for (int k = 0; k < k4; k++) {
    float4 av = Pr[k];
    float4 bv;
    bv = Q0[k]; acc0 += av.x * bv.x + av.y * bv.y + av.z * bv.z + av.w * bv.w;
    bv = Q1[k]; acc1 += av.x * bv.x + av.y * bv.y + av.z * bv.z + av.w * bv.w;
    bv = Q2[k]; acc2 += av.x * bv.x + av.y * bv.y + av.z * bv.z + av.w * bv.w;
    bv = Q3[k]; acc3 += av.x * bv.x + av.y * bv.y + av.z * bv.z + av.w * bv.w;
  }
  float* Cr = C + a * ldc + b0;
  Cr[0] = acc0 * scale; Cr[1] = acc1 * scale;
  Cr[2] = acc2 * scale; Cr[3] = acc3 * scale;
}

// Gauss-Jordan inverse of a 64x64, partial pivoting, single block (256 thr).
// Mm must point to shared memory of >= (64*SROW + 64) floats.
__device__ void gj_inverse(const float* __restrict__ in, float* __restrict__ out,
                           float* Mm) {
  __shared__ int s_piv;
  float* fcol = Mm + 64 * SROW;
  const int tid = threadIdx.x;
  for (int i = tid; i < 64 * 128; i += 256) {
    int r = i >> 7, c = i & 127;
    Mm[r * SROW + c] = (c < 64) ? in[r * 64 + c] : ((c - 64 == r) ? 1.0f : 0.0f);
  }
  __syncthreads();
  for (int p = 0; p < 64; p++) {
    if (tid == 0) {
      int best = p; float bv = fabsf(Mm[p * SROW + p]);
      for (int r = p + 1; r < 64; r++) {
        float v = fabsf(Mm[r * SROW + p]);
        if (v > bv) { bv = v; best = r; }
      }
      s_piv = best;
    }
    __syncthreads();
    int pr = s_piv;
    if (pr != p && tid < 128) {
      float t = Mm[p * SROW + tid];
      Mm[p * SROW + tid] = Mm[pr * SROW + tid];
      Mm[pr * SROW + tid] = t;
    }
    __syncthreads();
    float invp = 1.0f / Mm[p * SROW + p];
    __syncthreads();
    if (tid < 128) Mm[p * SROW + tid] *= invp;
    __syncthreads();
    if (tid < 64) fcol[tid] = Mm[tid * SROW + p];
    __syncthreads();
    for (int i = tid; i < 64 * 128; i += 256) {
      int r = i >> 7, c = i & 127;
      if (r != p) Mm[r * SROW + c] -= fcol[r] * Mm[p * SROW + c];
    }
    __syncthreads();
  }
  for (int i = tid; i < 64 * 64; i += 256) {
    int r = i >> 6, c = i & 63;
    out[r * 64 + c] = Mm[r * SROW + 64 + c];
  }
}

// ---------------- kernels ----------------

__global__ void zero_acc() {
  int i = blockIdx.x * 256 + threadIdx.x;
  if (i < 2 * KD * MDIM) ((float*)g_AP)[i] = 0.0f;
}

// A = tx @ fx, Py = ty @ fy  (split-K over VDIM with atomic accumulation)
__global__ void gemm_big(const float* __restrict__ fx, const float* __restrict__ fy,
                         const float* __restrict__ tx, const float* __restrict__ ty) {
  const int mt  = blockIdx.x;   // 0..3  (64-col tile of M)
  const int vs  = blockIdx.y;   // 0..KSPLIT-1
  const int mat = blockIdx.z;   // 0..1
  const float* __restrict__ F  = mat ? fy : fx;   // [VDIM][MDIM]
  const float* __restrict__ Wm = mat ? ty : tx;   // [KD][VDIM]
  float* out = g_AP[mat];
  const int m0 = mt * 64;
  const int v0 = vs * VCHUNK;
  __shared__ __align__(16) float Ws[8][64];
  __shared__ __align__(16) float Fs[8][64];
  const int tid = threadIdx.x;
  const int tr = (tid >> 4) << 2;
  const int tc = (tid & 15) << 2;
  float acc[4][4];
#pragma unroll
  for (int i = 0; i < 4; i++)
#pragma unroll
    for (int j = 0; j < 4; j++) acc[i][j] = 0.f;

  for (int vv = v0; vv < v0 + VCHUNK; vv += 8) {
    int idx = tid;
#pragma unroll
    for (int q = 0; q < 2; q++, idx += 256) {
      int kk = idx & 7, row = idx >> 3;
      Ws[kk][row] = Wm[row * VDIM + vv + kk];
      int kk2 = idx >> 6, col = idx & 63;
      Fs[kk2][col] = F[(vv + kk2) * MDIM + m0 + col];
    }
    __syncthreads();
#pragma unroll
    for (int kk = 0; kk < 8; kk++) {
      float4 av = *(const float4*)&Ws[kk][tr];
      float4 bv = *(const float4*)&Fs[kk][tc];
      acc[0][0] += av.x * bv.x; acc[0][1] += av.x * bv.y; acc[0][2] += av.x * bv.z; acc[0][3] += av.x * bv.w;
      acc[1][0] += av.y * bv.x; acc[1][1] += av.y * bv.y; acc[1][2] += av.y * bv.z; acc[1][3] += av.y * bv.w;
      acc[2][0] += av.z * bv.x; acc[2][1] += av.z * bv.y; acc[2][2] += av.z * bv.z; acc[2][3] += av.z * bv.w;
      acc[3][0] += av.w * bv.x; acc[3][1] += av.w * bv.y; acc[3][2] += av.w * bv.z; acc[3][3] += av.w * bv.w;
    }
    __syncthreads();
  }
#pragma unroll
  for (int i = 0; i < 4; i++)
#pragma unroll
    for (int j = 0; j < 4; j++)
      atomicAdd(&out[(tr + i) * MDIM + m0 + tc + j], acc[i][j]);
}

// task0: S = inv(sx); task1: H = sy^T sy; tasks 2-5: G = A A^T; 6-9: T1 = Py A^T
__global__ void stage1(const float* __restrict__ sx, const float* __restrict__ sy) {
  __shared__ __align__(16) float sh[64 * SROW + 64];
  const int task = blockIdx.x;
  const int tid = threadIdx.x;
  if (task == 0) {
    gj_inverse(sx, g_S, sh);
  } else if (task == 1) {
    for (int i = tid; i < 4096; i += 256) {
      int a = i >> 6, r = i & 63;
      sh[a * SROW + r] = sy[r * 64 + a];   // sh[a][i] = sy[i][a]
    }
    __syncthreads();
    for (int a0 = 0; a0 < 64; a0 += 16)
      mm_nt_16(sh, SROW, sh, SROW, 64, g_H, 64, a0, 1.0f);
  } else if (task < 6) {
    mm_nt_16(g_AP[0], MDIM, g_AP[0], MDIM, MDIM, g_G, 64, (task - 2) * 16, 1.0f);
  } else {
    mm_nt_16(g_AP[1], MDIM, g_AP[0], MDIM, MDIM, g_T1, 64, (task - 6) * 16, 1.0f);
  }
}

// task0: Hinv; task1: Ginv; tasks 2-4: M_j = S^T lx^j S (j=2,1,0); task5: HL/LHL
__global__ void stage2(const float* __restrict__ ex, const float* __restrict__ ey) {
  __shared__ __align__(16) float sh[64 * SROW + 64];
  const int task = blockIdx.x;
  const int tid = threadIdx.x;
  if (task == 0) {
    gj_inverse(g_H, g_Hinv, sh);
  } else if (task == 1) {
    gj_inverse(g_G, g_Ginv, sh);
  } else if (task < 5) {
    const int jc = (task - 2) * 64;   // 0 -> M2, 64 -> M1, 128 -> M0
    for (int i = tid; i < 4096; i += 256) {
      int t = i >> 6, ii = i & 63;
      float w = (task == 2) ? ex[ii] : ((task == 3) ? sqrtf(ex[ii]) : 1.0f);
      sh[t * SROW + ii] = g_S[ii * 64 + t] * w;   // sqrt-weighted S^T
    }
    __syncthreads();
    for (int a0 = 0; a0 < 64; a0 += 16)
      mm_nt_16(sh, SROW, sh, SROW, 64, g_Mcat + jc, 192, a0, 1.0f);
  } else {
    for (int i = tid; i < 4096; i += 256) {
      int r = i >> 6, c = i & 63;
      float h = g_H[i];
      g_HL[i]  = h * (ey[r] + ey[c]);
      g_LHL[i] = ey[r] * h * ey[c];
    }
  }
}

// tasks 0-2: N_j = M_j Ginv; task3: -Hinv HL; task4: Hinv LHL; task5: X0 = T1 Ginv
__global__ void stage3() {
  __shared__ __align__(16) float sh[64 * SROW + 64];
  const int task = blockIdx.x;
  const int tid = threadIdx.x;
  if (task < 3) {
    const int jc = task * 64;
    for (int i = tid; i < 4096; i += 256) {
      int b = i >> 6, u = i & 63;
      sh[b * SROW + u] = g_Ginv[u * 64 + b];
    }
    __syncthreads();
    for (int a0 = 0; a0 < 64; a0 += 16)
      mm_nt_16(g_Mcat + jc, 192, sh, SROW, 64, g_Ncat + jc, 192, a0, 1.0f);
  } else if (task < 5) {
    const float* src = (task == 3) ? g_HL : g_LHL;
    const float scale = (task == 3) ? -1.0f : 1.0f;
    const int off = (task == 3) ? 0 : 64;
    for (int i = tid; i < 4096; i += 256) {
      int b = i >> 6, u = i & 63;
      sh[b * SROW + u] = src[u * 64 + b];
    }
    __syncthreads();
    for (int a0 = 0; a0 < 64; a0 += 16)
      mm_nt_16(g_Hinv, 64, sh, SROW, 64, g_LP + off, 128, a0, scale);
  } else {
    for (int i = tid; i < 4096; i += 256) {
      int b = i >> 6, u = i & 63;
      sh[b * SROW + u] = g_Ginv[u * 64 + b];
    }
    __syncthreads();
    for (int a0 = 0; a0 < 64; a0 += 16)
      mm_nt_16(g_T1, 64, sh, SROW, 64, g_X0, 64, a0, 1.0f);
    __syncthreads();
    for (int i = tid; i < 4096; i += 256) g_X[i] = g_X0[i];
  }
}

// V = X @ Ncat  (per-block 64-column slab)
__global__ void iterA() {
  __shared__ __align__(16) float sh[64 * SROW];
  const int jc = blockIdx.x * 64;
  const int tid = threadIdx.x;
  for (int i = tid; i < 4096; i += 256) {
    int b = i >> 6, t = i & 63;
    sh[b * SROW + t] = g_Ncat[t * 192 + jc + b];
  }
  __syncthreads();
  for (int a0 = 0; a0 < 64; a0 += 16)
    mm_nt_16(g_X, 64, sh, SROW, 64, g_V + jc, 192, a0, 1.0f);
}

// X = X0 - lambda*( V[:,0:64] + [-P1|P0] @ [V[:,64:128]; V[:,128:192]] )
__global__ void iterB(float* __restrict__ outp) {
  __shared__ __align__(16) float VsT[64 * SROW];   // VsT[b][u], u in 0..127
  const int tid = threadIdx.x;
  for (int i = tid; i < 64 * 128; i += 256) {
    int b = i >> 7, u = i & 127;
    float v = (u < 64) ? g_V[u * 192 + 64 + b] : g_V[(u - 64) * 192 + 128 + b];
    VsT[b * SROW + u] = v;
  }
  __syncthreads();
  const int r0 = blockIdx.x * 16;
  const int a = r0 + (tid >> 4);
  const int b0 = (tid & 15) << 2;
  float acc[4] = {0.f, 0.f, 0.f, 0.f};
  const float4* LPr = (const float4*)(g_LP + a * 128);
  for (int k = 0; k < 32; k++) {
    float4 lp = LPr[k];
#pragma unroll
    for (int jj = 0; jj < 4; jj++) {
      float4 v = *(const float4*)(VsT + (b0 + jj) * SROW + k * 4);
      acc[jj] += lp.x * v.x + lp.y * v.y + lp.z * v.z + lp.w * v.w;
    }
  }
#pragma unroll
  for (int jj = 0; jj < 4; jj++) {
    int b = b0 + jj;
    float val = g_X0[a * 64 + b] - LMBDA * (g_V[a * 192 + b] + acc[jj]);
    g_X[a * 64 + b] = val;
    if (outp) outp[a * 64 + b] = val;
  }
}

// ---------------- launch ----------------
extern "C" void kernel_launch(void* const* d_in, const int* in_sizes, int n_in,
                              void* d_out, int out_size) {
  const float* fx = (const float*)d_in[0];   // [1,5000,256]
  const float* fy = (const float*)d_in[1];   // [1,5000,256]
  const float* ex = (const float*)d_in[2];   // [1,64]
  const float* ey = (const float*)d_in[3];   // [1,64]
  const float* tx = (const float*)d_in[4];   // [1,64,5000]
  const float* ty = (const float*)d_in[5];   // [1,64,5000]
  const float* sx = (const float*)d_in[6];   // [1,64,64]
  const float* sy = (const float*)d_in[7];   // [1,64,64]
  float* out = (float*)d_out;                // [1,64,64] float32

  zero_acc<<<128, 256>>>();
  gemm_big<<<dim3(4, KSPLIT, 2), 256>>>(fx, fy, tx, ty);
  stage1<<<10, 256>>>(sx, sy);
  stage2<<<6, 256>>>(ex, ey);
  stage3<<<6, 256>>>();
  for (int it = 0; it < NITER; it++) {
    iterA<<<3, 256>>>();
    iterB<<<4, 256>>>(it == NITER - 1 ? out : nullptr);
  }
}

// round 5
// speedup vs baseline: 1.4973x; 1.4973x over previous
#include <cuda_runtime.h>
#include <math.h>

#define KD 64
#define MDIM 256
#define VDIM 5000
#define LMBDA 0.001f
#define NITER 6
#define VCHUNK 200
#define KSPLIT 25
#define SROW 132   // padded shared row stride (multiple of 4)

// ---------------- device scratch (no allocation allowed) ----------------
__device__ float g_AP[2][KD * MDIM];     // [0]=A=tx@fx, [1]=Py=ty@fy
__device__ float g_S[KD * KD];           // inv(sx)
__device__ float g_H[KD * KD];           // sy^T sy
__device__ float g_G[KD * KD];           // A A^T
__device__ float g_T1[KD * KD];          // Py A^T
__device__ float g_Mcat[KD * 192];       // [M2 | M1 | M0]
__device__ float g_Ncat[KD * 192];       // [M2 Ginv | M1 Ginv | M0 Ginv]
__device__ float g_Hinv[KD * KD];
__device__ float g_Ginv[KD * KD];
__device__ float g_HL[KD * KD];          // H ly + ly H
__device__ float g_LHL[KD * KD];         // ly H ly
__device__ float g_LP[KD * 128];         // [-Hinv HL | Hinv LHL]
__device__ float g_X0[KD * KD];
__device__ float g_X[KD * KD];
__device__ float g_V[KD * 192];          // X @ Ncat

// ---------------- helpers ----------------

// C[a0..a0+15][0..63] = scale * sum_k P[a][k]*Q[b][k]; row strides ldp/ldq/ldc
// (multiples of 4). Requires blockDim.x == 256.
__device__ __forceinline__ void mm_nt_16(
    const float* __restrict__ P, int ldp,
    const float* __restrict__ Q, int ldq,
    int Klen, float* __restrict__ C, int ldc, int a0, float scale) {
  const int tid = threadIdx.x;
  const int a = a0 + (tid >> 4);
  const int b0 = (tid & 15) << 2;
  float acc0 = 0.f, acc1 = 0.f, acc2 = 0.f, acc3 = 0.f;
  const float4* Pr = (const float4*)(P + a * ldp);
  const float4* Q0 = (const float4*)(Q + (b0 + 0) * ldq);
  const float4* Q1 = (const float4*)(Q + (b0 + 1) * ldq);
  const float4* Q2 = (const float4*)(Q + (b0 + 2) * ldq);
  const float4* Q3 = (const float4*)(Q + (b0 + 3) * ldq);
  const int k4 = Klen >> 2;
  for (int k = 0; k < k4; k++) {
    float4 av = Pr[k];
    float4 bv;
    bv = Q0[k]; acc0 += av.x * bv.x + av.y * bv.y + av.z * bv.z + av.w * bv.w;
    bv = Q1[k]; acc1 += av.x * bv.x + av.y * bv.y + av.z * bv.z + av.w * bv.w;
    bv = Q2[k]; acc2 += av.x * bv.x + av.y * bv.y + av.z * bv.z + av.w * bv.w;
    bv = Q3[k]; acc3 += av.x * bv.x + av.y * bv.y + av.z * bv.z + av.w * bv.w;
  }
  float* Cr = C + a * ldc + b0;
  Cr[0] = acc0 * scale; Cr[1] = acc1 * scale;
  Cr[2] = acc2 * scale; Cr[3] = acc3 * scale;
}

// Register-resident in-place Gauss-Jordan inverse of a 64x64 (no pivoting;
// inputs are SPD or near-identity so elimination is stable). One block of
// 256 threads: thread owns column c = tid&63 and rows r = (tid>>6) + 4q.
// Per pivot: publish pivot row+col through shared (broadcast-friendly),
// then 16-element register update. 2 barriers per pivot.
__device__ void gj_inverse_reg(const float* __restrict__ in,
                               float* __restrict__ out) {
  __shared__ float prow[64];
  __shared__ float pcol[64];
  const int tid = threadIdx.x;
  const int r0 = tid >> 6;        // 0..3
  const int c  = tid & 63;
  float v[16];
#pragma unroll
  for (int q = 0; q < 16; q++) v[q] = in[(r0 + 4 * q) * 64 + c];

  for (int p = 0; p < 64; p++) {
    // publish pivot column (4 threads with c==p, one per r0)
    if (c == p) {
#pragma unroll
      for (int q = 0; q < 16; q++) pcol[r0 + 4 * q] = v[q];
    }
    // publish pivot row (64 threads with r0 == p&3, element q = p>>2)
    if (r0 == (p & 3)) prow[c] = v[p >> 2];
    __syncthreads();
    const float dinv = 1.0f / prow[p];
    const float prc = prow[c] * dinv;   // M[p][c] / piv
    if (c == p) {
#pragma unroll
      for (int q = 0; q < 16; q++) {
        int r = r0 + 4 * q;
        v[q] = (r == p) ? dinv : -v[q] * dinv;
      }
    } else {
#pragma unroll
      for (int q = 0; q < 16; q++) {
        int r = r0 + 4 * q;
        v[q] = (r == p) ? prc : fmaf(-pcol[r], prc, v[q]);
      }
    }
    __syncthreads();
  }
#pragma unroll
  for (int q = 0; q < 16; q++) out[(r0 + 4 * q) * 64 + c] = v[q];
}

// ---------------- kernels ----------------

__global__ void zero_acc() {
  int i = blockIdx.x * 256 + threadIdx.x;
  if (i < 2 * KD * MDIM) ((float*)g_AP)[i] = 0.0f;
}

// A = tx @ fx, Py = ty @ fy  (split-K over VDIM with atomic accumulation)
__global__ void gemm_big(const float* __restrict__ fx, const float* __restrict__ fy,
                         const float* __restrict__ tx, const float* __restrict__ ty) {
  const int mt  = blockIdx.x;   // 0..3  (64-col tile of M)
  const int vs  = blockIdx.y;   // 0..KSPLIT-1
  const int mat = blockIdx.z;   // 0..1
  const float* __restrict__ F  = mat ? fy : fx;   // [VDIM][MDIM]
  const float* __restrict__ Wm = mat ? ty : tx;   // [KD][VDIM]
  float* out = g_AP[mat];
  const int m0 = mt * 64;
  const int v0 = vs * VCHUNK;
  __shared__ __align__(16) float Ws[8][64];
  __shared__ __align__(16) float Fs[8][64];
  const int tid = threadIdx.x;
  const int tr = (tid >> 4) << 2;
  const int tc = (tid & 15) << 2;
  float acc[4][4];
#pragma unroll
  for (int i = 0; i < 4; i++)
#pragma unroll
    for (int j = 0; j < 4; j++) acc[i][j] = 0.f;

  for (int vv = v0; vv < v0 + VCHUNK; vv += 8) {
    int idx = tid;
#pragma unroll
    for (int q = 0; q < 2; q++, idx += 256) {
      int kk = idx & 7, row = idx >> 3;
      Ws[kk][row] = Wm[row * VDIM + vv + kk];
      int kk2 = idx >> 6, col = idx & 63;
      Fs[kk2][col] = F[(vv + kk2) * MDIM + m0 + col];
    }
    __syncthreads();
#pragma unroll
    for (int kk = 0; kk < 8; kk++) {
      float4 av = *(const float4*)&Ws[kk][tr];
      float4 bv = *(const float4*)&Fs[kk][tc];
      acc[0][0] += av.x * bv.x; acc[0][1] += av.x * bv.y; acc[0][2] += av.x * bv.z; acc[0][3] += av.x * bv.w;
      acc[1][0] += av.y * bv.x; acc[1][1] += av.y * bv.y; acc[1][2] += av.y * bv.z; acc[1][3] += av.y * bv.w;
      acc[2][0] += av.z * bv.x; acc[2][1] += av.z * bv.y; acc[2][2] += av.z * bv.z; acc[2][3] += av.z * bv.w;
      acc[3][0] += av.w * bv.x; acc[3][1] += av.w * bv.y; acc[3][2] += av.w * bv.z; acc[3][3] += av.w * bv.w;
    }
    __syncthreads();
  }
#pragma unroll
  for (int i = 0; i < 4; i++)
#pragma unroll
    for (int j = 0; j < 4; j++)
      atomicAdd(&out[(tr + i) * MDIM + m0 + tc + j], acc[i][j]);
}

// task0: S = inv(sx); task1: H = sy^T sy; tasks 2-5: G = A A^T; 6-9: T1 = Py A^T
__global__ void stage1(const float* __restrict__ sx, const float* __restrict__ sy) {
  __shared__ __align__(16) float sh[64 * SROW + 64];
  const int task = blockIdx.x;
  const int tid = threadIdx.x;
  if (task == 0) {
    gj_inverse_reg(sx, g_S);
  } else if (task == 1) {
    for (int i = tid; i < 4096; i += 256) {
      int a = i >> 6, r = i & 63;
      sh[a * SROW + r] = sy[r * 64 + a];   // sh[a][i] = sy[i][a]
    }
    __syncthreads();
    for (int a0 = 0; a0 < 64; a0 += 16)
      mm_nt_16(sh, SROW, sh, SROW, 64, g_H, 64, a0, 1.0f);
  } else if (task < 6) {
    mm_nt_16(g_AP[0], MDIM, g_AP[0], MDIM, MDIM, g_G, 64, (task - 2) * 16, 1.0f);
  } else {
    mm_nt_16(g_AP[1], MDIM, g_AP[0], MDIM, MDIM, g_T1, 64, (task - 6) * 16, 1.0f);
  }
}

// task0: Hinv; task1: Ginv; tasks 2-4: M_j = S^T lx^j S (j=2,1,0); task5: HL/LHL
__global__ void stage2(const float* __restrict__ ex, const float* __restrict__ ey) {
  __shared__ __align__(16) float sh[64 * SROW + 64];
  const int task = blockIdx.x;
  const int tid = threadIdx.x;
  if (task == 0) {
    gj_inverse_reg(g_H, g_Hinv);
  } else if (task == 1) {
    gj_inverse_reg(g_G, g_Ginv);
  } else if (task < 5) {
    const int jc = (task - 2) * 64;   // 0 -> M2, 64 -> M1, 128 -> M0
    for (int i = tid; i < 4096; i += 256) {
      int t = i >> 6, ii = i & 63;
      float w = (task == 2) ? ex[ii] : ((task == 3) ? sqrtf(ex[ii]) : 1.0f);
      sh[t * SROW + ii] = g_S[ii * 64 + t] * w;   // sqrt-weighted S^T
    }
    __syncthreads();
    for (int a0 = 0; a0 < 64; a0 += 16)
      mm_nt_16(sh, SROW, sh, SROW, 64, g_Mcat + jc, 192, a0, 1.0f);
  } else {
    for (int i = tid; i < 4096; i += 256) {
      int r = i >> 6, c = i & 63;
      float h = g_H[i];
      g_HL[i]  = h * (ey[r] + ey[c]);
      g_LHL[i] = ey[r] * h * ey[c];
    }
  }
}

// tasks 0-2: N_j = M_j Ginv; task3: -Hinv HL; task4: Hinv LHL; task5: X0 = T1 Ginv
__global__ void stage3() {
  __shared__ __align__(16) float sh[64 * SROW + 64];
  const int task = blockIdx.x;
  const int tid = threadIdx.x;
  if (task < 3) {
    const int jc = task * 64;
    for (int i = tid; i < 4096; i += 256) {
      int b = i >> 6, u = i & 63;
      sh[b * SROW + u] = g_Ginv[u * 64 + b];
    }
    __syncthreads();
    for (int a0 = 0; a0 < 64; a0 += 16)
      mm_nt_16(g_Mcat + jc, 192, sh, SROW, 64, g_Ncat + jc, 192, a0, 1.0f);
  } else if (task < 5) {
    const float* src = (task == 3) ? g_HL : g_LHL;
    const float scale = (task == 3) ? -1.0f : 1.0f;
    const int off = (task == 3) ? 0 : 64;
    for (int i = tid; i < 4096; i += 256) {
      int b = i >> 6, u = i & 63;
      sh[b * SROW + u] = src[u * 64 + b];
    }
    __syncthreads();
    for (int a0 = 0; a0 < 64; a0 += 16)
      mm_nt_16(g_Hinv, 64, sh, SROW, 64, g_LP + off, 128, a0, scale);
  } else {
    for (int i = tid; i < 4096; i += 256) {
      int b = i >> 6, u = i & 63;
      sh[b * SROW + u] = g_Ginv[u * 64 + b];
    }
    __syncthreads();
    for (int a0 = 0; a0 < 64; a0 += 16)
      mm_nt_16(g_T1, 64, sh, SROW, 64, g_X0, 64, a0, 1.0f);
    __syncthreads();
    for (int i = tid; i < 4096; i += 256) g_X[i] = g_X0[i];
  }
}

// V = X @ Ncat  (per-block 64-column slab)
__global__ void iterA() {
  __shared__ __align__(16) float sh[64 * SROW];
  const int jc = blockIdx.x * 64;
  const int tid = threadIdx.x;
  for (int i = tid; i < 4096; i += 256) {
    int b = i >> 6, t = i & 63;
    sh[b * SROW + t] = g_Ncat[t * 192 + jc + b];
  }
  __syncthreads();
  for (int a0 = 0; a0 < 64; a0 += 16)
    mm_nt_16(g_X, 64, sh, SROW, 64, g_V + jc, 192, a0, 1.0f);
}

// X = X0 - lambda*( V[:,0:64] + [-P1|P0] @ [V[:,64:128]; V[:,128:192]] )
__global__ void iterB(float* __restrict__ outp) {
  __shared__ __align__(16) float VsT[64 * SROW];   // VsT[b][u], u in 0..127
  const int tid = threadIdx.x;
  for (int i = tid; i < 64 * 128; i += 256) {
    int b = i >> 7, u = i & 127;
    float v = (u < 64) ? g_V[u * 192 + 64 + b] : g_V[(u - 64) * 192 + 128 + b];
    VsT[b * SROW + u] = v;
  }
  __syncthreads();
  const int r0 = blockIdx.x * 16;
  const int a = r0 + (tid >> 4);
  const int b0 = (tid & 15) << 2;
  float acc[4] = {0.f, 0.f, 0.f, 0.f};
  const float4* LPr = (const float4*)(g_LP + a * 128);
  for (int k = 0; k < 32; k++) {
    float4 lp = LPr[k];
#pragma unroll
    for (int jj = 0; jj < 4; jj++) {
      float4 v = *(const float4*)(VsT + (b0 + jj) * SROW + k * 4);
      acc[jj] += lp.x * v.x + lp.y * v.y + lp.z * v.z + lp.w * v.w;
    }
  }
#pragma unroll
  for (int jj = 0; jj < 4; jj++) {
    int b = b0 + jj;
    float val = g_X0[a * 64 + b] - LMBDA * (g_V[a * 192 + b] + acc[jj]);
    g_X[a * 64 + b] = val;
    if (outp) outp[a * 64 + b] = val;
  }
}

// ---------------- launch ----------------
extern "C" void kernel_launch(void* const* d_in, const int* in_sizes, int n_in,
                              void* d_out, int out_size) {
  const float* fx = (const float*)d_in[0];   // [1,5000,256]
  const float* fy = (const float*)d_in[1];   // [1,5000,256]
  const float* ex = (const float*)d_in[2];   // [1,64]
  const float* ey = (const float*)d_in[3];   // [1,64]
  const float* tx = (const float*)d_in[4];   // [1,64,5000]
  const float* ty = (const float*)d_in[5];   // [1,64,5000]
  const float* sx = (const float*)d_in[6];   // [1,64,64]
  const float* sy = (const float*)d_in[7];   // [1,64,64]
  float* out = (float*)d_out;                // [1,64,64] float32

  zero_acc<<<128, 256>>>();
  gemm_big<<<dim3(4, KSPLIT, 2), 256>>>(fx, fy, tx, ty);
  stage1<<<10, 256>>>(sx, sy);
  stage2<<<6, 256>>>(ex, ey);
  stage3<<<6, 256>>>();
  for (int it = 0; it < NITER; it++) {
    iterA<<<3, 256>>>();
    iterB<<<4, 256>>>(it == NITER - 1 ? out : nullptr);
  }
}